// round 3
// baseline (speedup 1.0000x reference)
#include <cuda_runtime.h>

// ---------------------------------------------------------------------------
// FlashMultiHeadAttention: x -> QKV GEMM -> RoPE -> flash attention -> proj
// B=4, T=2048, D=1024, H=16, DH=64, all fp32.
// ---------------------------------------------------------------------------

constexpr int Bb  = 4;
constexpr int T   = 2048;
constexpr int D   = 1024;
constexpr int H   = 16;
constexpr int DH  = 64;
constexpr int BHn = Bb * H;       // 64
constexpr int M   = Bb * T;       // 8192 rows
constexpr int KD  = D;            // 1024 (reduction dim of both GEMMs)
constexpr int NQKV = 3 * D;       // 3072

// Scratch (static __device__ allocation, allowed by harness rules)
__device__ float g_Q[(size_t)BHn * T * DH];   // [bh][t][d]
__device__ float g_K[(size_t)BHn * T * DH];
__device__ float g_V[(size_t)BHn * T * DH];
__device__ float g_AO[(size_t)M * D];         // attention output [b,t,h*dh]

// ---------------------------------------------------------------------------
// SGEMM: C[M,N] = A[M,KD] @ Bw[KD,N] + bias[N]
// MODE 0: A = Ain (=x), scatter result into g_Q/g_K/g_V per-head layout
// MODE 1: A = g_AO, write Cout row-major (d_out)
// 128x128x8 tiles, 256 threads, 8x8 per-thread micro-tile.
// ---------------------------------------------------------------------------
template <int MODE>
__global__ __launch_bounds__(256, 2)
void sgemm_kernel(const float* __restrict__ Ain,
                  const float* __restrict__ Bw,
                  const float* __restrict__ bias,
                  float* __restrict__ Cout,
                  int N)
{
    constexpr int BM = 128, BN = 128, BK = 8;
    __shared__ float As[BK][BM + 4];   // A stored transposed: As[k][m], pad kills store conflicts
    __shared__ float Bs[BK][BN];

    const float* A = (MODE == 1) ? g_AO : Ain;

    const int tid = threadIdx.x;
    const int m0 = blockIdx.y * BM;
    const int n0 = blockIdx.x * BN;
    const int tx = tid & 15;
    const int ty = tid >> 4;

    const int a_row = tid >> 1;          // 0..127
    const int a_col = (tid & 1) * 4;     // 0 or 4
    const int b_row = tid >> 5;          // 0..7
    const int b_col = (tid & 31) * 4;    // 0..124

    const float* Aptr = A + (size_t)(m0 + a_row) * KD + a_col;
    const float* Bptr = Bw + (size_t)b_row * N + n0 + b_col;

    float acc[8][8];
#pragma unroll
    for (int i = 0; i < 8; i++)
#pragma unroll
        for (int j = 0; j < 8; j++) acc[i][j] = 0.f;

    for (int k0 = 0; k0 < KD; k0 += BK) {
        float4 av = *(const float4*)Aptr;
        float4 bv = *(const float4*)Bptr;
        __syncthreads();
        As[a_col + 0][a_row] = av.x;
        As[a_col + 1][a_row] = av.y;
        As[a_col + 2][a_row] = av.z;
        As[a_col + 3][a_row] = av.w;
        *(float4*)&Bs[b_row][b_col] = bv;
        __syncthreads();
        Aptr += BK;
        Bptr += (size_t)BK * N;

#pragma unroll
        for (int kk = 0; kk < BK; kk++) {
            float af[8], bf[8];
            *(float4*)&af[0] = *(const float4*)&As[kk][ty * 8];
            *(float4*)&af[4] = *(const float4*)&As[kk][ty * 8 + 4];
            *(float4*)&bf[0] = *(const float4*)&Bs[kk][tx * 8];
            *(float4*)&bf[4] = *(const float4*)&Bs[kk][tx * 8 + 4];
#pragma unroll
            for (int i = 0; i < 8; i++)
#pragma unroll
                for (int j = 0; j < 8; j++)
                    acc[i][j] += af[i] * bf[j];
        }
    }

    float bfr[8];
#pragma unroll
    for (int j = 0; j < 8; j++) bfr[j] = bias[n0 + tx * 8 + j];

#pragma unroll
    for (int i = 0; i < 8; i++) {
        const int m = m0 + ty * 8 + i;
#pragma unroll
        for (int j = 0; j < 8; j++) {
            const int n = n0 + tx * 8 + j;
            const float v = acc[i][j] + bfr[j];
            if (MODE == 1) {
                Cout[(size_t)m * N + n] = v;
            } else {
                // n -> (sel, h, dd); m -> (b, t). Scatter to [bh][t][dd].
                const int sel = n >> 10;
                const int rem = n & 1023;
                const int h   = rem >> 6;
                const int dd  = rem & 63;
                const int b   = m >> 11;
                const int t   = m & 2047;
                float* P = (sel == 0) ? g_Q : (sel == 1) ? g_K : g_V;
                P[(((size_t)(b * H + h)) * T + t) * DH + dd] = v;
            }
        }
    }
}

// ---------------------------------------------------------------------------
// RoPE applied in-place to g_Q and g_K. Q additionally pre-scaled by DH^-0.5.
// One thread handles the (d, d+32) rotation pair. cos[t,d] == cos[t,d+32].
// Total threads = 2 * BHn * T * 32 = 2^23.
// ---------------------------------------------------------------------------
__global__ void rope_kernel(const float* __restrict__ cosT,
                            const float* __restrict__ sinT)
{
    const int idx = blockIdx.x * blockDim.x + threadIdx.x;
    const int d   = idx & 31;
    const int t   = (idx >> 5) & (T - 1);
    const int bh  = (idx >> 16) & (BHn - 1);
    const int arr = idx >> 22;          // 0 = Q, 1 = K
    float* P = arr ? g_K : g_Q;
    const size_t base = ((size_t)bh * T + t) * DH;
    const float u1 = P[base + d];
    const float u2 = P[base + d + 32];
    const float c  = cosT[t * DH + d];
    const float s  = sinT[t * DH + d];
    float o1 = u1 * c - u2 * s;
    float o2 = u2 * c + u1 * s;
    if (arr == 0) { o1 *= 0.125f; o2 *= 0.125f; }   // DH^-0.5 folded into Q
    P[base + d]      = o1;
    P[base + d + 32] = o2;
}

// ---------------------------------------------------------------------------
// Flash attention. One block: 128 query rows of one (b,h); loops over 64-row
// key tiles. 256 threads; thread (tx=tid&15, ty=tid>>4) owns rows ty*8..+7
// and columns {tx + 16*j, j=0..3} (strided -> conflict-free smem access).
// Online softmax state replicated across each 16-lane row group via shfl_xor.
// ---------------------------------------------------------------------------
constexpr int FBM = 128, FBN = 64;
constexpr int LDQ = 65, LDK = 65, LDV = 64, LDP = 65;
constexpr int SMEM_FLASH = (FBM * LDQ + FBN * LDK + FBN * LDV + FBM * LDP) * 4; // 99584 B

__global__ __launch_bounds__(256, 2)
void flash_kernel()
{
    extern __shared__ float sm[];
    float* Qs  = sm;                    // [FBM][LDQ]
    float* Kts = Qs + FBM * LDQ;        // [DH][LDK]  (K transposed: Kts[d][n])
    float* Vs  = Kts + FBN * LDK;       // [FBN][LDV] (Vs[n][d])
    float* Ps  = Vs + FBN * LDV;        // [FBM][LDP]

    const int tid = threadIdx.x;
    const int bh  = blockIdx.y;
    const int q0  = blockIdx.x * FBM;
    const int tx  = tid & 15;
    const int ty  = tid >> 4;
    const int r0  = ty * 8;

    const float* Qg = g_Q + ((size_t)bh * T + q0) * DH;
    const float* Kg = g_K + (size_t)bh * T * DH;
    const float* Vg = g_V + (size_t)bh * T * DH;

    // Load Q tile (128x64): 8 float4 per thread, scalar smem stores (ld=65)
#pragma unroll
    for (int i = 0; i < 8; i++) {
        const int idx = tid * 4 + i * 1024;
        const int r = idx >> 6, d = idx & 63;
        const float4 v = *(const float4*)(Qg + idx);
        Qs[r * LDQ + d + 0] = v.x;
        Qs[r * LDQ + d + 1] = v.y;
        Qs[r * LDQ + d + 2] = v.z;
        Qs[r * LDQ + d + 3] = v.w;
    }

    float m_i[8], l_i[8], o[8][4];
#pragma unroll
    for (int i = 0; i < 8; i++) {
        m_i[i] = -1e30f;
        l_i[i] = 0.f;
#pragma unroll
        for (int j = 0; j < 4; j++) o[i][j] = 0.f;
    }

    for (int n0 = 0; n0 < T; n0 += FBN) {
        __syncthreads();   // prev iteration's Kts/Vs/Ps reads complete
        // Load K tile transposed + V tile (each 64x64): 4 float4 per thread
#pragma unroll
        for (int i = 0; i < 4; i++) {
            const int idx = tid * 4 + i * 1024;
            const int n = idx >> 6, d = idx & 63;
            const float4 kv = *(const float4*)(Kg + (size_t)n0 * DH + idx);
            Kts[(d + 0) * LDK + n] = kv.x;
            Kts[(d + 1) * LDK + n] = kv.y;
            Kts[(d + 2) * LDK + n] = kv.z;
            Kts[(d + 3) * LDK + n] = kv.w;
            const float4 vv = *(const float4*)(Vg + (size_t)n0 * DH + idx);
            *(float4*)&Vs[n * LDV + d] = vv;
        }
        __syncthreads();

        // S = Q @ K^T  (Q already carries the 1/sqrt(DH) scale)
        float s[8][4];
#pragma unroll
        for (int i = 0; i < 8; i++)
#pragma unroll
            for (int j = 0; j < 4; j++) s[i][j] = 0.f;

#pragma unroll 4
        for (int k = 0; k < DH; k++) {
            float q[8], kf[4];
#pragma unroll
            for (int i = 0; i < 8; i++) q[i] = Qs[(r0 + i) * LDQ + k];
#pragma unroll
            for (int j = 0; j < 4; j++) kf[j] = Kts[k * LDK + tx + 16 * j];
#pragma unroll
            for (int i = 0; i < 8; i++)
#pragma unroll
                for (int j = 0; j < 4; j++)
                    s[i][j] += q[i] * kf[j];
        }

        // Online softmax (row groups of 16 lanes; xor masks <16 stay in-group)
#pragma unroll
        for (int i = 0; i < 8; i++) {
            float mx = fmaxf(fmaxf(s[i][0], s[i][1]), fmaxf(s[i][2], s[i][3]));
#pragma unroll
            for (int off = 1; off < 16; off <<= 1)
                mx = fmaxf(mx, __shfl_xor_sync(0xffffffffu, mx, off));
            const float mnew = fmaxf(m_i[i], mx);
            const float corr = __expf(m_i[i] - mnew);
            m_i[i] = mnew;
            float rs = 0.f;
#pragma unroll
            for (int j = 0; j < 4; j++) {
                s[i][j] = __expf(s[i][j] - mnew);
                rs += s[i][j];
            }
#pragma unroll
            for (int off = 1; off < 16; off <<= 1)
                rs += __shfl_xor_sync(0xffffffffu, rs, off);
            l_i[i] = l_i[i] * corr + rs;
#pragma unroll
            for (int j = 0; j < 4; j++) o[i][j] *= corr;
        }

        // Stage P to smem, then O += P @ V
#pragma unroll
        for (int i = 0; i < 8; i++)
#pragma unroll
            for (int j = 0; j < 4; j++)
                Ps[(r0 + i) * LDP + tx + 16 * j] = s[i][j];
        __syncthreads();

#pragma unroll 4
        for (int k = 0; k < FBN; k++) {
            float p[8], v[4];
#pragma unroll
            for (int i = 0; i < 8; i++) p[i] = Ps[(r0 + i) * LDP + k];
#pragma unroll
            for (int j = 0; j < 4; j++) v[j] = Vs[k * LDV + tx + 16 * j];
#pragma unroll
            for (int i = 0; i < 8; i++)
#pragma unroll
                for (int j = 0; j < 4; j++)
                    o[i][j] += p[i] * v[j];
        }
    }

    // Epilogue: normalize and write to [b, t, h*DH + c]
    const int b = bh >> 4;
    const int h = bh & 15;
#pragma unroll
    for (int i = 0; i < 8; i++) {
        const float inv = 1.f / l_i[i];
        const int t = q0 + r0 + i;
        const size_t rowbase = ((size_t)b * T + t) * D + h * DH;
#pragma unroll
        for (int j = 0; j < 4; j++)
            g_AO[rowbase + tx + 16 * j] = o[i][j] * inv;
    }
}

// ---------------------------------------------------------------------------
// Launch: qkv gemm -> rope -> flash -> proj gemm. Graph-capturable (launches
// only; no sync/alloc/memcpy). cudaFuncSetAttribute is idempotent, non-stream.
// ---------------------------------------------------------------------------
extern "C" void kernel_launch(void* const* d_in, const int* in_sizes, int n_in,
                              void* d_out, int out_size)
{
    (void)in_sizes; (void)n_in; (void)out_size;
    const float* x     = (const float*)d_in[0];
    const float* Wqkv  = (const float*)d_in[1];
    const float* bqkv  = (const float*)d_in[2];
    const float* Wproj = (const float*)d_in[3];
    const float* bproj = (const float*)d_in[4];
    const float* cosT  = (const float*)d_in[5];
    const float* sinT  = (const float*)d_in[6];
    float* out = (float*)d_out;

    sgemm_kernel<0><<<dim3(NQKV / 128, M / 128), 256>>>(x, Wqkv, bqkv, nullptr, NQKV);
    rope_kernel<<<(2 * BHn * T * 32) / 256, 256>>>(cosT, sinT);
    cudaFuncSetAttribute(flash_kernel, cudaFuncAttributeMaxDynamicSharedMemorySize, SMEM_FLASH);
    flash_kernel<<<dim3(T / FBM, BHn), 256, SMEM_FLASH>>>();
    sgemm_kernel<1><<<dim3(D / 128, M / 128), 256>>>(nullptr, Wproj, bproj, out, D);
}